// round 1
// baseline (speedup 1.0000x reference)
#include <cuda_runtime.h>
#include <math_constants.h>

#define NPTS 4096
#define TOPK 4
#define WARPS_PER_BLOCK 16
#define NTHREADS (WARPS_PER_BLOCK * 32)

__device__ __forceinline__ bool pless(float da, int ia, float db, int ib) {
    // strict total order: (dist asc, index asc) — matches jax.lax.top_k stability
    return (da < db) || (da == db && ia < ib);
}

#define CAS(dx, ix, dy, iy)                                        \
    do {                                                           \
        if (!pless(dx, ix, dy, iy)) {                              \
            float _t = dx; dx = dy; dy = _t;                       \
            int _u = ix; ix = iy; iy = _u;                         \
        }                                                          \
    } while (0)

__global__ void __launch_bounds__(NTHREADS)
nn_tag_pool_kernel(const float2* __restrict__ obs1,
                   const float2* __restrict__ obs2,
                   const float*  __restrict__ W,
                   const float*  __restrict__ bias,
                   float* __restrict__ out)
{
    __shared__ float2 spts[NPTS];

    const int tid = threadIdx.x;
    for (int t = tid; t < NPTS; t += NTHREADS) spts[t] = obs2[t];
    __syncthreads();

    const int warp = tid >> 5;
    const int lane = tid & 31;
    const int i = blockIdx.x * WARPS_PER_BLOCK + warp;   // query row

    // Per-lane weight constants for the fused linear: o = output channel 0..7
    const int o = lane & 7;
    const float w0 = W[o * 6 + 0];
    const float w1 = W[o * 6 + 1];
    const float w3 = W[o * 6 + 3];
    const float w4 = W[o * 6 + 4];
    const float c  = W[o * 6 + 2] + W[o * 6 + 5] + bias[o];  // tag columns are constant 1

    const float2 q = spts[i];

    // Register-resident sorted top-4 (ascending dist)
    float d0 = CUDART_INF_F, d1 = CUDART_INF_F, d2 = CUDART_INF_F, d3 = CUDART_INF_F;
    int   i0 = 0x7fffffff,  i1 = 0x7fffffff,  i2 = 0x7fffffff,  i3 = 0x7fffffff;

    #pragma unroll 4
    for (int j = lane; j < NPTS; j += 32) {
        float2 p = spts[j];
        float dx = p.x - q.x;
        float dy = p.y - q.y;
        float dv = fmaf(dx, dx, fmaf(dy, dy, 1.0f));
        if (j != i && dv < d3) {
            // insertion sort into sorted-of-4; strict < keeps earlier (smaller) j stable
            d3 = dv; i3 = j;
            if (d3 < d2) { float t = d3; d3 = d2; d2 = t; int u = i3; i3 = i2; i2 = u; }
            if (d2 < d1) { float t = d2; d2 = d1; d1 = t; int u = i2; i2 = i1; i1 = u; }
            if (d1 < d0) { float t = d1; d1 = d0; d0 = t; int u = i1; i1 = i0; i0 = u; }
        }
    }

    // Butterfly merge across the warp: merge two sorted-4 lists -> sorted-4.
    // Concat(A asc, reverse(B asc)) is bitonic; stride-4 min stage picks the 4
    // smallest as a bitonic-4, then a 4-element bitonic sort finishes.
    #pragma unroll
    for (int off = 16; off >= 1; off >>= 1) {
        float e0 = __shfl_xor_sync(0xffffffffu, d0, off);
        float e1 = __shfl_xor_sync(0xffffffffu, d1, off);
        float e2 = __shfl_xor_sync(0xffffffffu, d2, off);
        float e3 = __shfl_xor_sync(0xffffffffu, d3, off);
        int   j0 = __shfl_xor_sync(0xffffffffu, i0, off);
        int   j1 = __shfl_xor_sync(0xffffffffu, i1, off);
        int   j2 = __shfl_xor_sync(0xffffffffu, i2, off);
        int   j3 = __shfl_xor_sync(0xffffffffu, i3, off);

        float m0, m1, m2, m3; int n0, n1, n2, n3;
        if (pless(d0, i0, e3, j3)) { m0 = d0; n0 = i0; } else { m0 = e3; n0 = j3; }
        if (pless(d1, i1, e2, j2)) { m1 = d1; n1 = i1; } else { m1 = e2; n1 = j2; }
        if (pless(d2, i2, e1, j1)) { m2 = d2; n2 = i2; } else { m2 = e1; n2 = j1; }
        if (pless(d3, i3, e0, j0)) { m3 = d3; n3 = i3; } else { m3 = e0; n3 = j0; }

        CAS(m0, n0, m2, n2);
        CAS(m1, n1, m3, n3);
        CAS(m0, n0, m1, n1);
        CAS(m2, n2, m3, n3);

        d0 = m0; d1 = m1; d2 = m2; d3 = m3;
        i0 = n0; i1 = n1; i2 = n2; i3 = n3;
    }
    // All lanes now hold the identical sorted top-4 (butterfly => converged).

    // Epilogue: lane kk*8+o computes output channel o of neighbor kk.
    const int kk = lane >> 3;
    const int j = (kk == 0) ? i0 : (kk == 1) ? i1 : (kk == 2) ? i2 : i3;

    const float2 pj  = spts[j];
    const float2 a1j = obs1[j];
    const float2 a1i = obs1[i];

    const float px = pj.x - q.x;
    const float py = pj.y - q.y;
    const float vx = (pj.x - a1j.x) - (q.x - a1i.x);   // vel[j] - vel[i]
    const float vy = (pj.y - a1j.y) - (q.y - a1i.y);

    float r = fmaf(px, w0, fmaf(py, w1, fmaf(vx, w3, fmaf(vy, w4, c))));
    out[i * 32 + lane] = fmaxf(r, 0.0f);
}

extern "C" void kernel_launch(void* const* d_in, const int* in_sizes, int n_in,
                              void* d_out, int out_size) {
    const float2* obs1 = (const float2*)d_in[0];
    const float2* obs2 = (const float2*)d_in[1];
    const float*  W    = (const float*)d_in[2];
    const float*  bias = (const float*)d_in[3];
    float* out = (float*)d_out;

    dim3 grid(NPTS / WARPS_PER_BLOCK);   // 256 blocks
    dim3 block(NTHREADS);                // 512 threads = 16 warps
    nn_tag_pool_kernel<<<grid, block>>>(obs1, obs2, W, bias, out);
}

// round 2
// speedup vs baseline: 1.6328x; 1.6328x over previous
#include <cuda_runtime.h>
#include <math_constants.h>

#define NPTS 4096
#define WARPS_PER_BLOCK 16
#define NTHREADS (WARPS_PER_BLOCK * 32)
#define FULL 0xffffffffu

// ---- packed f32x2 helpers (sm_103a) ----
__device__ __forceinline__ unsigned long long pack2(float x, float y) {
    unsigned long long r;
    asm("mov.b64 %0, {%1, %2};" : "=l"(r) : "f"(x), "f"(y));
    return r;
}

// returns (p.x + nq.x)^2 + 1 + (p.y + nq.y)^2  where nq = packed(-qx,-qy)
__device__ __forceinline__ float dist2_packed(unsigned long long p, unsigned long long nq) {
    unsigned long long d, s;
    const unsigned long long one_lo = 0x3f800000ULL;  // (lo=1.0f, hi=0.0f)
    asm("add.rn.f32x2 %0, %1, %2;" : "=l"(d) : "l"(p), "l"(nq));
    asm("fma.rn.f32x2 %0, %1, %2, %3;" : "=l"(s) : "l"(d), "l"(d), "l"(one_lo));
    float lo, hi;
    asm("mov.b64 {%0, %1}, %2;" : "=f"(lo), "=f"(hi) : "l"(s));
    return lo + hi;  // dx^2 + 1 + dy^2
}

__global__ void __launch_bounds__(NTHREADS)
nn_tag_pool_kernel(const float2* __restrict__ obs1,
                   const float2* __restrict__ obs2,
                   const float*  __restrict__ W,
                   const float*  __restrict__ bias,
                   float* __restrict__ out)
{
    __shared__ __align__(16) float2 spts[NPTS];

    const int tid = threadIdx.x;
    {   // vectorized stage of all 4096 points (32 KB)
        const float4* src = (const float4*)obs2;
        float4* dst = (float4*)spts;
        #pragma unroll
        for (int t = tid; t < NPTS / 2; t += NTHREADS) dst[t] = src[t];
    }
    __syncthreads();

    const int warp = tid >> 5;
    const int lane = tid & 31;
    const int i = blockIdx.x * WARPS_PER_BLOCK + warp;   // query row

    // Fused linear constants: lane = kk*8 + o
    const int o = lane & 7;
    const float w0 = W[o * 6 + 0];
    const float w1 = W[o * 6 + 1];
    const float w3 = W[o * 6 + 3];
    const float w4 = W[o * 6 + 4];
    const float c  = W[o * 6 + 2] + W[o * 6 + 5] + bias[o];

    const float2 q = spts[i];
    const unsigned long long nq = pack2(-q.x, -q.y);

    // Warp-uniform sorted top-4 (ascending dist; ties by smaller index first)
    float d0 = CUDART_INF_F, d1 = CUDART_INF_F, d2 = CUDART_INF_F, d3 = CUDART_INF_F;
    int   i0 = 0, i1 = 0, i2 = 0, i3 = 0;

    const float4* sp4 = (const float4*)spts;

    #pragma unroll 2
    for (int it = 0; it < NPTS / 64; ++it) {   // 64 iterations, 2 points/lane
        float4 v = sp4[it * 32 + lane];
        unsigned long long pa = pack2(v.x, v.y);
        unsigned long long pb = pack2(v.z, v.w);
        float dva = dist2_packed(pa, nq);
        float dvb = dist2_packed(pb, nq);

        unsigned m = __ballot_sync(FULL, fminf(dva, dvb) < d3);
        // warp-uniform branch: no divergence
        while (m) {
            int r = __ffs(m) - 1;
            m &= m - 1;
            float xa = __shfl_sync(FULL, dva, r);
            float xb = __shfl_sync(FULL, dvb, r);
            int ja = (it * 32 + r) * 2;

            // inserts in strictly increasing j; strict '<' => exact top_k tie order
            if (ja != i && xa < d3) {
                d3 = xa; i3 = ja;
                if (d3 < d2) { float t=d3; d3=d2; d2=t; int u=i3; i3=i2; i2=u; }
                if (d2 < d1) { float t=d2; d2=d1; d1=t; int u=i2; i2=i1; i1=u; }
                if (d1 < d0) { float t=d1; d1=d0; d0=t; int u=i1; i1=i0; i0=u; }
            }
            int jb = ja + 1;
            if (jb != i && xb < d3) {
                d3 = xb; i3 = jb;
                if (d3 < d2) { float t=d3; d3=d2; d2=t; int u=i3; i3=i2; i2=u; }
                if (d2 < d1) { float t=d2; d2=d1; d1=t; int u=i2; i2=i1; i1=u; }
                if (d1 < d0) { float t=d1; d1=d0; d0=t; int u=i1; i1=i0; i0=u; }
            }
        }
    }

    // Epilogue: list already warp-uniform (no merge needed).
    // lane kk*8+o computes output channel o of neighbor kk.
    const int kk = lane >> 3;
    const int j = (kk == 0) ? i0 : (kk == 1) ? i1 : (kk == 2) ? i2 : i3;

    const float2 pj  = spts[j];
    const float2 a1j = obs1[j];
    const float2 a1i = obs1[i];

    const float px = pj.x - q.x;
    const float py = pj.y - q.y;
    const float vx = (pj.x - a1j.x) - (q.x - a1i.x);   // vel[j] - vel[i]
    const float vy = (pj.y - a1j.y) - (q.y - a1i.y);

    float r = fmaf(px, w0, fmaf(py, w1, fmaf(vx, w3, fmaf(vy, w4, c))));
    out[i * 32 + lane] = fmaxf(r, 0.0f);
}

extern "C" void kernel_launch(void* const* d_in, const int* in_sizes, int n_in,
                              void* d_out, int out_size) {
    const float2* obs1 = (const float2*)d_in[0];
    const float2* obs2 = (const float2*)d_in[1];
    const float*  W    = (const float*)d_in[2];
    const float*  bias = (const float*)d_in[3];
    float* out = (float*)d_out;

    dim3 grid(NPTS / WARPS_PER_BLOCK);   // 256 blocks
    dim3 block(NTHREADS);                // 512 threads = 16 warps
    nn_tag_pool_kernel<<<grid, block>>>(obs1, obs2, W, bias, out);
}